// round 5
// baseline (speedup 1.0000x reference)
#include <cuda_runtime.h>
#include <cuda_fp16.h>
#include <cstdint>

#define NROWS  128
#define NCOLS  524288
#define NANG   8128
#define TILE_N 128
#define NTILES (NCOLS / TILE_N)   // 4096

#define NSEG   32
#define SEGLEN (NANG / NSEG)      // 254
#define MATSZ  (NROWS * NROWS)    // 16384

// ============================================================================
// Device globals (no cudaMalloc allowed)
// Slots: level0 -> 0..15, level1 -> 16..23, level2 -> 24..27, level3 -> 28..29
// ============================================================================
__device__ __half g_Rhi[MATSZ];
__device__ __half g_Rlo[MATSZ];
__device__ __half g_Mhi[30 * MATSZ];
__device__ __half g_Mlo[30 * MATSZ];
__device__ int    g_flags[32];            // zero-init; reset by gemm block 0

// ============================================================================
// Common PTX helpers
// ============================================================================
__device__ __forceinline__ uint32_t smem_u32(const void* p) {
    uint32_t a;
    asm("{ .reg .u64 t; cvta.to.shared.u64 t, %1; cvt.u32.u64 %0, t; }"
        : "=r"(a) : "l"(p));
    return a;
}
__device__ __forceinline__ void cp_async16(uint32_t dst, const void* src) {
    asm volatile("cp.async.cg.shared.global [%0], [%1], 16;"
                 :: "r"(dst), "l"(src) : "memory");
}
#define CP_COMMIT()  asm volatile("cp.async.commit_group;" ::: "memory")
#define CP_WAIT0()   asm volatile("cp.async.wait_group 0;" ::: "memory")
#define CP_WAIT1()   asm volatile("cp.async.wait_group 1;" ::: "memory")

__device__ __forceinline__ void ldsm4t(uint32_t& r0, uint32_t& r1,
                                       uint32_t& r2, uint32_t& r3, uint32_t addr)
{
    asm volatile("ldmatrix.sync.aligned.m8n8.x4.trans.shared.b16 "
                 "{%0,%1,%2,%3}, [%4];"
                 : "=r"(r0), "=r"(r1), "=r"(r2), "=r"(r3) : "r"(addr));
}
__device__ __forceinline__ void mma16816(float* d, const uint32_t* a,
                                         uint32_t b0, uint32_t b1)
{
    asm volatile("mma.sync.aligned.m16n8k16.row.col.f32.f16.f16.f32 "
                 "{%0,%1,%2,%3}, {%4,%5,%6,%7}, {%8,%9}, {%0,%1,%2,%3};"
                 : "+f"(d[0]), "+f"(d[1]), "+f"(d[2]), "+f"(d[3])
                 : "r"(a[0]), "r"(a[1]), "r"(a[2]), "r"(a[3]),
                   "r"(b0), "r"(b1));
}
__device__ __forceinline__ void split_pack(float v0, float v1,
                                           uint32_t& hw, uint32_t& lw)
{
    __half h0 = __float2half_rn(v0);
    __half h1 = __float2half_rn(v1);
    __half l0 = __float2half_rn(v0 - __half2float(h0));
    __half l1 = __float2half_rn(v1 - __half2float(h1));
    hw = (uint32_t)__half_as_ushort(h0) | ((uint32_t)__half_as_ushort(h1) << 16);
    lw = (uint32_t)__half_as_ushort(l0) | ((uint32_t)__half_as_ushort(l1) << 16);
}

#define PITCH_B 272            // fp16 tile row bytes: 256 + 16 pad

// 3-term MMA block: acc += Ahi*Bhi + Alo*Bhi + Ahi*Blo over full 128x128x128
__device__ __forceinline__ void mma_3term(float acc[16][4],
                                          const uint32_t ahi[8][4],
                                          const uint32_t alo[8][4],
                                          uint32_t bhi_s, uint32_t blo_s,
                                          uint32_t loff)
{
    #pragma unroll
    for (int ks = 0; ks < 8; ks++) {
        const uint32_t rowo = (uint32_t)(ks * 16) * PITCH_B + loff;
        #pragma unroll
        for (int nb = 0; nb < 8; nb++) {
            uint32_t h0, h1, h2, h3, l0, l1, l2, l3;
            ldsm4t(h0, h1, h2, h3, bhi_s + rowo + nb * 32);
            ldsm4t(l0, l1, l2, l3, blo_s + rowo + nb * 32);
            mma16816(acc[2 * nb    ], ahi[ks], h0, h1);
            mma16816(acc[2 * nb + 1], ahi[ks], h2, h3);
            mma16816(acc[2 * nb    ], alo[ks], h0, h1);
            mma16816(acc[2 * nb + 1], alo[ks], h2, h3);
            mma16816(acc[2 * nb    ], ahi[ks], l0, l1);
            mma16816(acc[2 * nb + 1], ahi[ks], l2, l3);
        }
    }
}

// epilogue: split fp32 acc -> fp16 hi/lo, store to Chi/Clo (row-major 128x128)
__device__ __forceinline__ void store_split(const float acc[16][4],
                                            __half* Chi, __half* Clo,
                                            int r0, int kc)
{
    #pragma unroll
    for (int a = 0; a < 16; a++) {
        int col = (a >> 1) * 16 + (a & 1) * 8 + kc;
        #pragma unroll
        for (int h2 = 0; h2 < 2; h2++) {
            int row = r0 + h2 * 8;
            uint32_t hw, lw;
            split_pack(acc[a][2 * h2], acc[a][2 * h2 + 1], hw, lw);
            *(uint32_t*)&Chi[row * 128 + col] = hw;
            *(uint32_t*)&Clo[row * 128 + col] = lw;
        }
    }
}

// ============================================================================
// Fused build kernel: 16 CTAs x 256 threads.
//  Phase 1: two Givens chains per CTA (segments 2b, 2b+1), fp32 in SMEM.
//  Phase 2: local combine P_b = M_{2b+1} @ M_{2b} (tensor cores) -> slot b.
//  Phase 3: 4 tree levels across CTAs via global flags -> g_Rhi/g_Rlo.
// ============================================================================
#define OFF_SEGA  0
#define OFF_SEGB  65536
#define OFF_CSA   131072
#define OFF_CSB   133120
#define OFF_BHI_B 135168
#define OFF_BLO_B (135168 + 34816)
#define SMEM_BUILD (135168 + 2 * 34816)   // 204800 B

__global__ void __launch_bounds__(256, 1)
build_R_fused(const float* __restrict__ angles)
{
    extern __shared__ char smb[];
    const uint32_t sbase = smem_u32(smb);
    const int tid   = threadIdx.x;
    const int w     = tid >> 5;
    const int lane  = tid & 31;
    const int group = tid >> 7;          // 0 or 1
    const int j     = tid & 127;
    const int b     = blockIdx.x;

    float*  segA = (float*)(smb + OFF_SEGA);
    float*  segB = (float*)(smb + OFF_SEGB);
    float*  Rs   = group ? segB : segA;
    float2* cs   = (float2*)(smb + (group ? OFF_CSB : OFF_CSA));

    // ---- Phase 1: chains ----
    const int s  = 2 * b + group;
    const int lo = s * SEGLEN;

    for (int k = j; k < SEGLEN; k += 128) {
        float sn, c;
        sincosf(angles[lo + k], &sn, &c);
        cs[k] = make_float2(c, sn);
    }
    for (int r = 0; r < NROWS; r++)
        Rs[r * NROWS + j] = (r == j) ? 1.0f : 0.0f;
    __syncthreads();

    {
        int p = 0, cum = 0;
        while (cum + (127 - p) <= lo) { cum += 127 - p; p++; }
        int q = p + 1 + (lo - cum);

        float rp = Rs[p * NROWS + j];
        #pragma unroll 4
        for (int kk = 0; kk < SEGLEN; kk++) {
            float2 a = cs[kk];
            float rq = Rs[q * NROWS + j];
            Rs[q * NROWS + j] = fmaf(a.y, rp, a.x * rq);
            rp = fmaf(a.x, rp, -a.y * rq);
            if (++q == NROWS) {
                Rs[p * NROWS + j] = rp;
                p++;
                if (p < NROWS - 1) { q = p + 1; rp = Rs[p * NROWS + j]; }
            }
        }
        if (p < NROWS - 1) Rs[p * NROWS + j] = rp;
    }
    __syncthreads();

    const uint32_t bhi_s = sbase + OFF_BHI_B;
    const uint32_t blo_s = sbase + OFF_BLO_B;
    const int r0 = w * 16 + (lane >> 2);
    const int kc = (lane & 3) * 2;
    const uint32_t loff = (uint32_t)((lane & 7) + ((lane >> 3) & 1) * 8) * PITCH_B
                        + (uint32_t)((lane >> 4) & 1) * 16;

    uint32_t ahi[8][4], alo[8][4];
    float acc[16][4];

    // ---- Phase 2: local combine  P_b = segB @ segA ----
    // stage B = segA as fp16 hi/lo tiles
    for (int i = tid; i < 8192; i += 256) {
        int k = i >> 6, np = i & 63;
        float2 x = *(const float2*)&segA[k * 128 + np * 2];
        uint32_t hw, lw;
        split_pack(x.x, x.y, hw, lw);
        *(uint32_t*)(smb + OFF_BHI_B + k * PITCH_B + np * 4) = hw;
        *(uint32_t*)(smb + OFF_BLO_B + k * PITCH_B + np * 4) = lw;
    }
    // A fragments from segB (fp32 smem), split in registers
    #pragma unroll
    for (int ks = 0; ks < 8; ks++) {
        int kb = ks * 16 + kc;
        float2 v;
        v = *(const float2*)&segB[(r0    ) * 128 + kb    ]; split_pack(v.x, v.y, ahi[ks][0], alo[ks][0]);
        v = *(const float2*)&segB[(r0 + 8) * 128 + kb    ]; split_pack(v.x, v.y, ahi[ks][1], alo[ks][1]);
        v = *(const float2*)&segB[(r0    ) * 128 + kb + 8]; split_pack(v.x, v.y, ahi[ks][2], alo[ks][2]);
        v = *(const float2*)&segB[(r0 + 8) * 128 + kb + 8]; split_pack(v.x, v.y, ahi[ks][3], alo[ks][3]);
    }
    __syncthreads();

    #pragma unroll
    for (int a = 0; a < 16; a++)
        #pragma unroll
        for (int q2 = 0; q2 < 4; q2++) acc[a][q2] = 0.0f;
    mma_3term(acc, ahi, alo, bhi_s, blo_s, loff);
    store_split(acc, g_Mhi + (size_t)b * MATSZ, g_Mlo + (size_t)b * MATSZ, r0, kc);
    __threadfence();
    __syncthreads();
    if (tid == 0) atomicExch(&g_flags[b], 1);

    // ---- Phase 3: tree levels across CTAs ----
    int nprod = 8, src_base = 0, dst_base = 16;
    #pragma unroll 1
    for (int L = 1; L <= 4; L++) {
        if (b >= nprod) return;
        const int sA = src_base + 2 * b + 1;   // left (A) operand slot
        const int sB = src_base + 2 * b;       // right (B) operand slot

        if (tid == 0) {
            while (atomicAdd(&g_flags[sA], 0) == 0) {}
            while (atomicAdd(&g_flags[sB], 0) == 0) {}
        }
        __syncthreads();
        __threadfence();

        // stage B from global slot
        {
            const uint4* Bh = (const uint4*)(g_Mhi + (size_t)sB * MATSZ);
            const uint4* Bl = (const uint4*)(g_Mlo + (size_t)sB * MATSZ);
            for (int i = tid; i < 2048; i += 256) {
                int k = i >> 4, c = i & 15;
                *(uint4*)(smb + OFF_BHI_B + k * PITCH_B + c * 16) = Bh[i];
                *(uint4*)(smb + OFF_BLO_B + k * PITCH_B + c * 16) = Bl[i];
            }
        }
        // A fragments from global slot
        {
            const __half* Ah = g_Mhi + (size_t)sA * MATSZ;
            const __half* Al = g_Mlo + (size_t)sA * MATSZ;
            #pragma unroll
            for (int ks = 0; ks < 8; ks++) {
                int kb = ks * 16 + kc;
                ahi[ks][0] = *(const uint32_t*)&Ah[(r0    ) * 128 + kb    ];
                ahi[ks][1] = *(const uint32_t*)&Ah[(r0 + 8) * 128 + kb    ];
                ahi[ks][2] = *(const uint32_t*)&Ah[(r0    ) * 128 + kb + 8];
                ahi[ks][3] = *(const uint32_t*)&Ah[(r0 + 8) * 128 + kb + 8];
                alo[ks][0] = *(const uint32_t*)&Al[(r0    ) * 128 + kb    ];
                alo[ks][1] = *(const uint32_t*)&Al[(r0 + 8) * 128 + kb    ];
                alo[ks][2] = *(const uint32_t*)&Al[(r0    ) * 128 + kb + 8];
                alo[ks][3] = *(const uint32_t*)&Al[(r0 + 8) * 128 + kb + 8];
            }
        }
        __syncthreads();

        #pragma unroll
        for (int a = 0; a < 16; a++)
            #pragma unroll
            for (int q2 = 0; q2 < 4; q2++) acc[a][q2] = 0.0f;
        mma_3term(acc, ahi, alo, bhi_s, blo_s, loff);

        if (L == 4) {
            store_split(acc, g_Rhi, g_Rlo, r0, kc);
            return;
        }
        store_split(acc, g_Mhi + (size_t)(dst_base + b) * MATSZ,
                         g_Mlo + (size_t)(dst_base + b) * MATSZ, r0, kc);
        __threadfence();
        __syncthreads();
        if (tid == 0) atomicExch(&g_flags[dst_base + b], 1);

        src_base = dst_base;
        dst_base += nprod;
        nprod >>= 1;
    }
}

// ============================================================================
// Gemm kernel: out = diag(mus) * (R @ X), mma.sync fp16 2-term split,
// 2 CTAs/SM, split-group cp.async so convert overlaps the load tail.
// Also resets g_flags for the next replay (block 0).
// ============================================================================
#define RAW_PITCH 512
#define OFF_RAW   0
#define OFF_BHI   65536
#define SMEM2     (65536 + 34816)   // 100352 -> 2 CTAs/SM

__device__ __forceinline__ void issue_half(const float* __restrict__ X,
                                           int t, uint32_t raw_s, int tid, int half)
{
    const size_t c0 = (size_t)t * TILE_N;
    #pragma unroll
    for (int jj = 0; jj < 8; jj++) {
        int c  = tid + jj * 256;       // 0..2047
        int k  = (c >> 5) + half * 64;
        int ch = c & 31;
        cp_async16(raw_s + k * RAW_PITCH + ch * 16,
                   X + (size_t)k * NCOLS + c0 + ch * 4);
    }
    CP_COMMIT();
}

__global__ void __launch_bounds__(256, 2)
gemm_kernel(const float* __restrict__ X, const float* __restrict__ mus,
            float* __restrict__ out)
{
    extern __shared__ char smem[];
    const uint32_t sbase = smem_u32(smem);
    const int tid  = threadIdx.x;
    const int w    = tid >> 5;
    const int lane = tid & 31;

    if (blockIdx.x == 0 && tid < 32) g_flags[tid] = 0;   // reset for next replay

    const int r0 = w * 16 + (lane >> 2);
    const int kc = (lane & 3) * 2;
    uint32_t ahi[8][4], alo[8][4];
    #pragma unroll
    for (int ks = 0; ks < 8; ks++) {
        int kb = ks * 16 + kc;
        ahi[ks][0] = *(const uint32_t*)&g_Rhi[(r0    ) * 128 + kb    ];
        ahi[ks][1] = *(const uint32_t*)&g_Rhi[(r0 + 8) * 128 + kb    ];
        ahi[ks][2] = *(const uint32_t*)&g_Rhi[(r0    ) * 128 + kb + 8];
        ahi[ks][3] = *(const uint32_t*)&g_Rhi[(r0 + 8) * 128 + kb + 8];
        alo[ks][0] = *(const uint32_t*)&g_Rlo[(r0    ) * 128 + kb    ];
        alo[ks][1] = *(const uint32_t*)&g_Rlo[(r0 + 8) * 128 + kb    ];
        alo[ks][2] = *(const uint32_t*)&g_Rlo[(r0    ) * 128 + kb + 8];
        alo[ks][3] = *(const uint32_t*)&g_Rlo[(r0 + 8) * 128 + kb + 8];
    }
    const float s0 = mus[r0];
    const float s1 = mus[r0 + 8];

    const uint32_t loff = (uint32_t)((lane & 7) + ((lane >> 3) & 1) * 8) * PITCH_B
                        + (uint32_t)((lane >> 4) & 1) * 16;
    const uint32_t bhi_s = sbase + OFF_BHI;
    const float*   raw   = (const float*)(smem + OFF_RAW);

    const int stride = gridDim.x;
    int t = blockIdx.x;
    if (t >= NTILES) return;

    issue_half(X, t, sbase + OFF_RAW, tid, 0);
    issue_half(X, t, sbase + OFF_RAW, tid, 1);

    for (; t < NTILES; t += stride) {
        // first half arrived -> convert while second half still in flight
        CP_WAIT1();
        __syncthreads();
        #pragma unroll
        for (int i = 0; i < 16; i++) {
            int e  = tid + i * 256;          // pairs of rows 0..63
            int k  = e >> 6;
            int np = e & 63;
            float2 x = *(const float2*)(raw + k * 128 + np * 2);
            __half h0 = __float2half_rn(x.x);
            __half h1 = __float2half_rn(x.y);
            uint32_t hw = (uint32_t)__half_as_ushort(h0)
                        | ((uint32_t)__half_as_ushort(h1) << 16);
            *(uint32_t*)(smem + OFF_BHI + k * PITCH_B + np * 4) = hw;
        }
        CP_WAIT0();
        __syncthreads();
        #pragma unroll
        for (int i = 0; i < 16; i++) {
            int e  = tid + i * 256;          // pairs of rows 64..127
            int k  = (e >> 6) + 64;
            int np = e & 63;
            float2 x = *(const float2*)(raw + k * 128 + np * 2);
            __half h0 = __float2half_rn(x.x);
            __half h1 = __float2half_rn(x.y);
            uint32_t hw = (uint32_t)__half_as_ushort(h0)
                        | ((uint32_t)__half_as_ushort(h1) << 16);
            *(uint32_t*)(smem + OFF_BHI + k * PITCH_B + np * 4) = hw;
        }
        __syncthreads();                 // Bhi ready; raw fully consumed

        int tn = t + stride;
        if (tn < NTILES) {
            issue_half(X, tn, sbase + OFF_RAW, tid, 0);   // overlaps MMA
            issue_half(X, tn, sbase + OFF_RAW, tid, 1);
        }

        #pragma unroll
        for (int pass = 0; pass < 2; pass++) {
            float acc[8][4];
            #pragma unroll
            for (int a = 0; a < 8; a++)
                #pragma unroll
                for (int q2 = 0; q2 < 4; q2++) acc[a][q2] = 0.0f;

            #pragma unroll
            for (int ks = 0; ks < 8; ks++) {
                const uint32_t rowo = (uint32_t)(ks * 16) * PITCH_B + loff
                                    + (uint32_t)pass * 128;
                #pragma unroll
                for (int nb = 0; nb < 4; nb++) {
                    uint32_t b0, b1, b2, b3;
                    ldsm4t(b0, b1, b2, b3, bhi_s + rowo + nb * 32);
                    mma16816(acc[2 * nb    ], ahi[ks], b0, b1);
                    mma16816(acc[2 * nb + 1], ahi[ks], b2, b3);
                    mma16816(acc[2 * nb    ], alo[ks], b0, b1);
                    mma16816(acc[2 * nb + 1], alo[ks], b2, b3);
                }
            }

            const size_t c0 = (size_t)t * TILE_N + pass * 64 + kc;
            float* o0 = out + (size_t)(r0    ) * NCOLS + c0;
            float* o1 = out + (size_t)(r0 + 8) * NCOLS + c0;
            #pragma unroll
            for (int a = 0; a < 8; a++) {
                int coff = (a >> 1) * 16 + (a & 1) * 8;
                float2 v0 = make_float2(s0 * acc[a][0], s0 * acc[a][1]);
                float2 v1 = make_float2(s1 * acc[a][2], s1 * acc[a][3]);
                *(float2*)(o0 + coff) = v0;
                *(float2*)(o1 + coff) = v1;
            }
        }
        __syncthreads();                 // Bhi consumed before next convert
    }
}

// ============================================================================
// Launch
// ============================================================================
extern "C" void kernel_launch(void* const* d_in, const int* in_sizes, int n_in,
                              void* d_out, int out_size)
{
    const float* X      = (const float*)d_in[0];
    const float* angles = (const float*)d_in[1];
    const float* mus    = (const float*)d_in[2];
    float* out          = (float*)d_out;

    cudaFuncSetAttribute(build_R_fused,
                         cudaFuncAttributeMaxDynamicSharedMemorySize, SMEM_BUILD);
    cudaFuncSetAttribute(gemm_kernel,
                         cudaFuncAttributeMaxDynamicSharedMemorySize, SMEM2);

    int sm_count = 148;
    cudaDeviceGetAttribute(&sm_count, cudaDevAttrMultiProcessorCount, 0);
    int grid = sm_count * 2;
    if (grid > NTILES) grid = NTILES;

    build_R_fused<<<16, 256, SMEM_BUILD>>>(angles);
    gemm_kernel<<<grid, 256, SMEM2>>>(X, mus, out);
}

// round 6
// speedup vs baseline: 1.0111x; 1.0111x over previous
#include <cuda_runtime.h>
#include <cuda_fp16.h>
#include <cstdint>

#define NROWS  128
#define NCOLS  524288
#define NANG   8128
#define TILE_N 128
#define NTILES (NCOLS / TILE_N)   // 4096

#define NSEG   32
#define SEGLEN (NANG / NSEG)      // 254
#define MATSZ  (NROWS * NROWS)    // 16384

#define PITCH_B 272               // fp16 tile row bytes: 256 + 16 pad

// ============================================================================
// Device globals (no cudaMalloc allowed)
// Slot banks: level0 -> 0..15, L1 -> 16..23, L2 -> 24..27, L3 -> 28..29
// ============================================================================
__device__ __half g_Rhi[MATSZ];
__device__ __half g_Mhi[30 * MATSZ];
__device__ __half g_Mlo[30 * MATSZ];
__device__ int    g_bar[8];               // zero-init; reset by gemm block 0

// ============================================================================
// Common PTX helpers
// ============================================================================
__device__ __forceinline__ uint32_t smem_u32(const void* p) {
    uint32_t a;
    asm("{ .reg .u64 t; cvta.to.shared.u64 t, %1; cvt.u32.u64 %0, t; }"
        : "=r"(a) : "l"(p));
    return a;
}
__device__ __forceinline__ void cp_async16(uint32_t dst, const void* src) {
    asm volatile("cp.async.cg.shared.global [%0], [%1], 16;"
                 :: "r"(dst), "l"(src) : "memory");
}
#define CP_COMMIT()  asm volatile("cp.async.commit_group;" ::: "memory")
#define CP_WAIT0()   asm volatile("cp.async.wait_group 0;" ::: "memory")

__device__ __forceinline__ void ldsm4t(uint32_t& r0, uint32_t& r1,
                                       uint32_t& r2, uint32_t& r3, uint32_t addr)
{
    asm volatile("ldmatrix.sync.aligned.m8n8.x4.trans.shared.b16 "
                 "{%0,%1,%2,%3}, [%4];"
                 : "=r"(r0), "=r"(r1), "=r"(r2), "=r"(r3) : "r"(addr));
}
__device__ __forceinline__ void mma16816(float* d, const uint32_t* a,
                                         uint32_t b0, uint32_t b1)
{
    asm volatile("mma.sync.aligned.m16n8k16.row.col.f32.f16.f16.f32 "
                 "{%0,%1,%2,%3}, {%4,%5,%6,%7}, {%8,%9}, {%0,%1,%2,%3};"
                 : "+f"(d[0]), "+f"(d[1]), "+f"(d[2]), "+f"(d[3])
                 : "r"(a[0]), "r"(a[1]), "r"(a[2]), "r"(a[3]),
                   "r"(b0), "r"(b1));
}
__device__ __forceinline__ void split_pack(float v0, float v1,
                                           uint32_t& hw, uint32_t& lw)
{
    __half h0 = __float2half_rn(v0);
    __half h1 = __float2half_rn(v1);
    __half l0 = __float2half_rn(v0 - __half2float(h0));
    __half l1 = __float2half_rn(v1 - __half2float(h1));
    hw = (uint32_t)__half_as_ushort(h0) | ((uint32_t)__half_as_ushort(h1) << 16);
    lw = (uint32_t)__half_as_ushort(l0) | ((uint32_t)__half_as_ushort(l1) << 16);
}

// 3-term MMA: acc += Ahi*Bhi + Alo*Bhi + Ahi*Blo over K=128, N = nblk16*16
__device__ __forceinline__ void mma_3term_n(float (*acc)[4],
                                            const uint32_t (*ahi)[4],
                                            const uint32_t (*alo)[4],
                                            uint32_t bhi_s, uint32_t blo_s,
                                            uint32_t loff, int nblk16)
{
    #pragma unroll
    for (int ks = 0; ks < 8; ks++) {
        const uint32_t rowo = (uint32_t)(ks * 16) * PITCH_B + loff;
        #pragma unroll 4
        for (int nb = 0; nb < nblk16; nb++) {
            uint32_t h0, h1, h2, h3, l0, l1, l2, l3;
            ldsm4t(h0, h1, h2, h3, bhi_s + rowo + nb * 32);
            ldsm4t(l0, l1, l2, l3, blo_s + rowo + nb * 32);
            mma16816(acc[2 * nb    ], ahi[ks], h0, h1);
            mma16816(acc[2 * nb + 1], ahi[ks], h2, h3);
            mma16816(acc[2 * nb    ], alo[ks], h0, h1);
            mma16816(acc[2 * nb + 1], alo[ks], h2, h3);
            mma16816(acc[2 * nb    ], ahi[ks], l0, l1);
            mma16816(acc[2 * nb + 1], ahi[ks], l2, l3);
        }
    }
}
// split fp32 acc -> fp16 hi/lo, store nblk8 n8-blocks starting at colbase
__device__ __forceinline__ void store_split_n(const float (*acc)[4],
                                              __half* Chi, __half* Clo,
                                              int r0, int kc, int colbase,
                                              int nblk8)
{
    #pragma unroll 4
    for (int a = 0; a < nblk8; a++) {
        int col = colbase + (a >> 1) * 16 + (a & 1) * 8 + kc;
        #pragma unroll
        for (int h2 = 0; h2 < 2; h2++) {
            int row = r0 + h2 * 8;
            uint32_t hw, lw;
            split_pack(acc[a][2 * h2], acc[a][2 * h2 + 1], hw, lw);
            *(uint32_t*)&Chi[row * 128 + col] = hw;
            *(uint32_t*)&Clo[row * 128 + col] = lw;
        }
    }
}

// ============================================================================
// Build kernel: 16 CTAs x 256 threads.
//  Phase 1: two Givens chains per CTA (segments 2b, 2b+1), fp32 in SMEM.
//  Phase 2: local combine P_b = M_{2b+1} @ M_{2b} -> slot b.
//  Phase 3: 4 tree levels, each N-SLICED across all 16 CTAs, global barrier
//           between levels. Final level writes g_Rhi.
// ============================================================================
#define OFF_SEGA   0
#define OFF_SEGB   65536
#define OFF_CSA    131072
#define OFF_CSB    133120
#define OFF_BHI_B  135168
#define OFF_BLO_B  (135168 + 34816)
#define SMEM_BUILD (135168 + 2 * 34816)   // 204800 B

__device__ __forceinline__ void grid_bar(int idx, int target, int tid)
{
    __threadfence();
    __syncthreads();
    if (tid == 0) {
        atomicAdd(&g_bar[idx], 1);
        while (atomicAdd(&g_bar[idx], 0) < target) {}
    }
    __syncthreads();
}

__global__ void __launch_bounds__(256, 1)
build_R_fused(const float* __restrict__ angles)
{
    extern __shared__ char smb[];
    const uint32_t sbase = smem_u32(smb);
    const int tid   = threadIdx.x;
    const int w     = tid >> 5;
    const int lane  = tid & 31;
    const int group = tid >> 7;          // 0 or 1
    const int j     = tid & 127;
    const int b     = blockIdx.x;

    float*  segA = (float*)(smb + OFF_SEGA);
    float*  segB = (float*)(smb + OFF_SEGB);
    float*  Rs   = group ? segB : segA;
    float2* cs   = (float2*)(smb + (group ? OFF_CSB : OFF_CSA));

    // ---- Phase 1: two chains per CTA ----
    const int s  = 2 * b + group;
    const int lo = s * SEGLEN;

    for (int k = j; k < SEGLEN; k += 128) {
        float sn, c;
        sincosf(angles[lo + k], &sn, &c);
        cs[k] = make_float2(c, sn);
    }
    for (int r = 0; r < NROWS; r++)
        Rs[r * NROWS + j] = (r == j) ? 1.0f : 0.0f;
    __syncthreads();

    {
        int p = 0, cum = 0;
        while (cum + (127 - p) <= lo) { cum += 127 - p; p++; }
        int q = p + 1 + (lo - cum);

        float rp = Rs[p * NROWS + j];
        #pragma unroll 4
        for (int kk = 0; kk < SEGLEN; kk++) {
            float2 a = cs[kk];
            float rq = Rs[q * NROWS + j];
            Rs[q * NROWS + j] = fmaf(a.y, rp, a.x * rq);
            rp = fmaf(a.x, rp, -a.y * rq);
            if (++q == NROWS) {
                Rs[p * NROWS + j] = rp;
                p++;
                if (p < NROWS - 1) { q = p + 1; rp = Rs[p * NROWS + j]; }
            }
        }
        if (p < NROWS - 1) Rs[p * NROWS + j] = rp;
    }
    __syncthreads();

    const uint32_t bhi_s = sbase + OFF_BHI_B;
    const uint32_t blo_s = sbase + OFF_BLO_B;
    const int r0 = w * 16 + (lane >> 2);
    const int kc = (lane & 3) * 2;
    const uint32_t loff = (uint32_t)((lane & 7) + ((lane >> 3) & 1) * 8) * PITCH_B
                        + (uint32_t)((lane >> 4) & 1) * 16;

    uint32_t ahi[8][4], alo[8][4];
    float acc[16][4];

    // ---- Phase 2: local combine  P_b = segB @ segA -> slot b ----
    for (int i = tid; i < 8192; i += 256) {
        int k = i >> 6, np = i & 63;
        float2 x = *(const float2*)&segA[k * 128 + np * 2];
        uint32_t hw, lw;
        split_pack(x.x, x.y, hw, lw);
        *(uint32_t*)(smb + OFF_BHI_B + k * PITCH_B + np * 4) = hw;
        *(uint32_t*)(smb + OFF_BLO_B + k * PITCH_B + np * 4) = lw;
    }
    #pragma unroll
    for (int ks = 0; ks < 8; ks++) {
        int kb = ks * 16 + kc;
        float2 v;
        v = *(const float2*)&segB[(r0    ) * 128 + kb    ]; split_pack(v.x, v.y, ahi[ks][0], alo[ks][0]);
        v = *(const float2*)&segB[(r0 + 8) * 128 + kb    ]; split_pack(v.x, v.y, ahi[ks][1], alo[ks][1]);
        v = *(const float2*)&segB[(r0    ) * 128 + kb + 8]; split_pack(v.x, v.y, ahi[ks][2], alo[ks][2]);
        v = *(const float2*)&segB[(r0 + 8) * 128 + kb + 8]; split_pack(v.x, v.y, ahi[ks][3], alo[ks][3]);
    }
    __syncthreads();

    #pragma unroll
    for (int a = 0; a < 16; a++)
        #pragma unroll
        for (int q2 = 0; q2 < 4; q2++) acc[a][q2] = 0.0f;
    mma_3term_n(acc, ahi, alo, bhi_s, blo_s, loff, 8);
    store_split_n(acc, g_Mhi + (size_t)b * MATSZ, g_Mlo + (size_t)b * MATSZ,
                  r0, kc, 0, 16);
    grid_bar(0, 16, tid);

    // ---- Phase 3: sliced tree levels ----
    const int srcb_arr[4]  = {0, 16, 24, 28};
    const int dstb_arr[4]  = {16, 24, 28, 0};
    const int nprod_arr[4] = {8, 4, 2, 1};
    const int cpp_arr[4]   = {2, 4, 8, 8};

    #pragma unroll 1
    for (int L = 0; L < 4; L++) {
        const int cpp  = cpp_arr[L];
        const int Nsl  = 128 / cpp;                 // 64,32,16,16
        const bool act = b < nprod_arr[L] * cpp;

        if (act) {
            const int prod = b / cpp;
            const int sl   = b - prod * cpp;
            const int sA = srcb_arr[L] + 2 * prod + 1;
            const int sB = srcb_arr[L] + 2 * prod;

            // stage B slice: rows k=0..127, cols [sl*Nsl, sl*Nsl+Nsl)
            const int nch = Nsl >> 3;               // 16B chunks per row
            const char* Bh = (const char*)(g_Mhi + (size_t)sB * MATSZ);
            const char* Bl = (const char*)(g_Mlo + (size_t)sB * MATSZ);
            for (int i = tid; i < 128 * nch; i += 256) {
                int k = i / nch, c = i - k * nch;
                *(uint4*)(smb + OFF_BHI_B + k * PITCH_B + c * 16) =
                    *(const uint4*)(Bh + k * 256 + sl * Nsl * 2 + c * 16);
                *(uint4*)(smb + OFF_BLO_B + k * PITCH_B + c * 16) =
                    *(const uint4*)(Bl + k * 256 + sl * Nsl * 2 + c * 16);
            }
            // A fragments
            const __half* Ah = g_Mhi + (size_t)sA * MATSZ;
            const __half* Al = g_Mlo + (size_t)sA * MATSZ;
            #pragma unroll
            for (int ks = 0; ks < 8; ks++) {
                int kb = ks * 16 + kc;
                ahi[ks][0] = *(const uint32_t*)&Ah[(r0    ) * 128 + kb    ];
                ahi[ks][1] = *(const uint32_t*)&Ah[(r0 + 8) * 128 + kb    ];
                ahi[ks][2] = *(const uint32_t*)&Ah[(r0    ) * 128 + kb + 8];
                ahi[ks][3] = *(const uint32_t*)&Ah[(r0 + 8) * 128 + kb + 8];
                alo[ks][0] = *(const uint32_t*)&Al[(r0    ) * 128 + kb    ];
                alo[ks][1] = *(const uint32_t*)&Al[(r0 + 8) * 128 + kb    ];
                alo[ks][2] = *(const uint32_t*)&Al[(r0    ) * 128 + kb + 8];
                alo[ks][3] = *(const uint32_t*)&Al[(r0 + 8) * 128 + kb + 8];
            }
            __syncthreads();

            #pragma unroll
            for (int a = 0; a < 16; a++)
                #pragma unroll
                for (int q2 = 0; q2 < 4; q2++) acc[a][q2] = 0.0f;
            mma_3term_n(acc, ahi, alo, bhi_s, blo_s, loff, Nsl >> 4);

            if (L == 3) {
                store_split_n(acc, g_Rhi, g_Mlo + (size_t)29 * MATSZ,  // lo -> scratch
                              r0, kc, sl * Nsl, Nsl >> 3);
            } else {
                store_split_n(acc, g_Mhi + (size_t)(dstb_arr[L] + prod) * MATSZ,
                                   g_Mlo + (size_t)(dstb_arr[L] + prod) * MATSZ,
                              r0, kc, sl * Nsl, Nsl >> 3);
            }
        }
        if (L < 3) grid_bar(1 + L, 16, tid);
    }
}

// ============================================================================
// Gemm: out = diag(mus) * (R @ X).  1-term fp16 mma (Rhi only).
// 512 threads, 1 CTA/SM, warp grid 4(M) x 4(N): M=32, N=32 per warp ->
// ldsm/B-smem traffic halved vs M16x8warps. Epilogue staged in XOR-swizzled
// SMEM -> STG.128 coalesced stores.
// ============================================================================
#define RAW_PITCH 512
#define OFF_RAW   0
#define OFF_BHI   65536
#define OFF_STAGE 100352
#define SMEM2     (100352 + 65536)    // 165888 B

__device__ __forceinline__ void issue_tile_load512(const float* __restrict__ X,
                                                   int t, uint32_t raw_s, int tid)
{
    const size_t c0 = (size_t)t * TILE_N;
    #pragma unroll
    for (int jj = 0; jj < 8; jj++) {
        int c  = tid + jj * 512;       // 16B-chunk index 0..4095
        int k  = c >> 5;
        int ch = c & 31;
        cp_async16(raw_s + k * RAW_PITCH + ch * 16,
                   X + (size_t)k * NCOLS + c0 + ch * 4);
    }
    CP_COMMIT();
}

__global__ void __launch_bounds__(512, 1)
gemm_kernel(const float* __restrict__ X, const float* __restrict__ mus,
            float* __restrict__ out)
{
    extern __shared__ char smem[];
    const uint32_t sbase = smem_u32(smem);
    const int tid  = threadIdx.x;
    const int w    = tid >> 5;
    const int lane = tid & 31;

    if (blockIdx.x == 0 && tid < 8) g_bar[tid] = 0;   // reset for next replay

    const int mg = w & 3;        // M-group: rows [32mg, 32mg+32)
    const int ng = w >> 2;       // N-group: cols [32ng, 32ng+32)
    const int cn = ng * 32;
    const int kc = (lane & 3) * 2;
    const int rq = lane >> 2;    // row within m16 block

    // A fragments (Rhi only): 2 m16 blocks x 8 k-steps x 4 regs = 64 regs
    uint32_t afr[2][8][4];
    float    sc[2][2];
    #pragma unroll
    for (int mb = 0; mb < 2; mb++) {
        const int rr = mg * 32 + mb * 16 + rq;
        sc[mb][0] = mus[rr];
        sc[mb][1] = mus[rr + 8];
        #pragma unroll
        for (int ks = 0; ks < 8; ks++) {
            int kb = ks * 16 + kc;
            afr[mb][ks][0] = *(const uint32_t*)&g_Rhi[(rr    ) * 128 + kb    ];
            afr[mb][ks][1] = *(const uint32_t*)&g_Rhi[(rr + 8) * 128 + kb    ];
            afr[mb][ks][2] = *(const uint32_t*)&g_Rhi[(rr    ) * 128 + kb + 8];
            afr[mb][ks][3] = *(const uint32_t*)&g_Rhi[(rr + 8) * 128 + kb + 8];
        }
    }

    const uint32_t loff = (uint32_t)((lane & 7) + ((lane >> 3) & 1) * 8) * PITCH_B
                        + (uint32_t)((lane >> 4) & 1) * 16
                        + (uint32_t)cn * 2;
    const uint32_t bhi_s = sbase + OFF_BHI;
    const float*   raw   = (const float*)(smem + OFF_RAW);

    const int stride = gridDim.x;
    int t = blockIdx.x;
    if (t >= NTILES) return;

    issue_tile_load512(X, t, sbase + OFF_RAW, tid);

    for (; t < NTILES; t += stride) {
        CP_WAIT0();
        __syncthreads();                 // raw tile visible

        // convert raw fp32 -> fp16 (hi only)
        #pragma unroll
        for (int i = 0; i < 16; i++) {
            int e  = tid + i * 512;      // pair index 0..8191
            int k  = e >> 6;
            int np = e & 63;
            float2 x = *(const float2*)(raw + k * 128 + np * 2);
            __half h0 = __float2half_rn(x.x);
            __half h1 = __float2half_rn(x.y);
            uint32_t hw = (uint32_t)__half_as_ushort(h0)
                        | ((uint32_t)__half_as_ushort(h1) << 16);
            *(uint32_t*)(smem + OFF_BHI + k * PITCH_B + np * 4) = hw;
        }
        __syncthreads();                 // Bhi ready; raw consumed

        int tn = t + stride;
        if (tn < NTILES)
            issue_tile_load512(X, tn, sbase + OFF_RAW, tid);   // overlaps MMA

        // ---- MMA: acc = Rhi * Xhi ----
        float acc[2][4][4];
        #pragma unroll
        for (int mb = 0; mb < 2; mb++)
            #pragma unroll
            for (int a = 0; a < 4; a++)
                #pragma unroll
                for (int q2 = 0; q2 < 4; q2++) acc[mb][a][q2] = 0.0f;

        #pragma unroll
        for (int ks = 0; ks < 8; ks++) {
            const uint32_t rowo = (uint32_t)(ks * 16) * PITCH_B + loff;
            #pragma unroll
            for (int nb = 0; nb < 2; nb++) {
                uint32_t b0, b1, b2, b3;
                ldsm4t(b0, b1, b2, b3, bhi_s + rowo + nb * 32);
                #pragma unroll
                for (int mb = 0; mb < 2; mb++) {
                    mma16816(acc[mb][2 * nb    ], afr[mb][ks], b0, b1);
                    mma16816(acc[mb][2 * nb + 1], afr[mb][ks], b2, b3);
                }
            }
        }

        // ---- stage to SMEM (XOR-swizzled 16B units), scale by mus ----
        #pragma unroll
        for (int mb = 0; mb < 2; mb++) {
            #pragma unroll
            for (int a = 0; a < 4; a++) {
                int col = cn + a * 8 + kc;
                #pragma unroll
                for (int h2 = 0; h2 < 2; h2++) {
                    int row = mg * 32 + mb * 16 + rq + h2 * 8;
                    float2 v = make_float2(sc[mb][h2] * acc[mb][a][2 * h2],
                                           sc[mb][h2] * acc[mb][a][2 * h2 + 1]);
                    uint32_t off = (uint32_t)row * 512
                                 + ((((uint32_t)(col >> 2)) ^ (row & 7)) << 4)
                                 + (col & 3) * 4;
                    *(float2*)(smem + OFF_STAGE + off) = v;
                }
            }
        }
        __syncthreads();                 // stage visible; ldsm done -> Bhi free

        // ---- coalesced output: LDS.128 + STG.128 ----
        {
            const size_t c0 = (size_t)t * TILE_N;
            #pragma unroll
            for (int i = 0; i < 8; i++) {
                int idx = tid + i * 512;       // 16B unit index 0..4095
                int row = idx >> 5;
                int u   = idx & 31;
                float4 v = *(const float4*)(smem + OFF_STAGE + row * 512
                                            + ((u ^ (row & 7)) << 4));
                *(float4*)(out + (size_t)row * NCOLS + c0 + u * 4) = v;
            }
        }
        // next iter's convert-sync orders stage reuse; no extra sync needed
    }
}

// ============================================================================
// Launch
// ============================================================================
extern "C" void kernel_launch(void* const* d_in, const int* in_sizes, int n_in,
                              void* d_out, int out_size)
{
    const float* X      = (const float*)d_in[0];
    const float* angles = (const float*)d_in[1];
    const float* mus    = (const float*)d_in[2];
    float* out          = (float*)d_out;

    cudaFuncSetAttribute(build_R_fused,
                         cudaFuncAttributeMaxDynamicSharedMemorySize, SMEM_BUILD);
    cudaFuncSetAttribute(gemm_kernel,
                         cudaFuncAttributeMaxDynamicSharedMemorySize, SMEM2);

    int sm_count = 148;
    cudaDeviceGetAttribute(&sm_count, cudaDevAttrMultiProcessorCount, 0);
    int grid = sm_count;
    if (grid > NTILES) grid = NTILES;

    build_R_fused<<<16, 256, SMEM_BUILD>>>(angles);
    gemm_kernel<<<grid, 512, SMEM2>>>(X, mus, out);
}